// round 16
// baseline (speedup 1.0000x reference)
#include <cuda_runtime.h>
#include <cuda_fp16.h>
#include <cstdint>

// Problem constants
#define NN      50000
#define EDGES   800000
#define F_IN    500

// ---------------------------------------------------------------------------
// Device scratch
// ---------------------------------------------------------------------------
__device__ __half g_h0[NN * 128];
__device__ __half g_h1[NN * 128];
__device__ __half g_h2[NN * 256];
__device__ __half g_aggh[NN * 128];
__device__ float  g_agg[NN * 40];
__device__ float  g_t3r3[NN * 80];

__device__ int g_deg[NN];
__device__ int g_rowptr[NN + 1];
__device__ int g_cursor[NN];
__device__ int g_csr[EDGES];

// Weights: Bt[n][k] (K-major, transposed), fp16
__device__ __half g_B0h[128 * 512];
__device__ __half g_B1h[128 * 256];
__device__ __half g_B2h[256 * 256];
__device__ __half g_B3h[128 * 256];

// ---------------------------------------------------------------------------
// PTX helpers
// ---------------------------------------------------------------------------
__device__ __forceinline__ uint32_t s2u(const void* p) {
    uint32_t a;
    asm("{ .reg .u64 t; cvta.to.shared.u64 t, %1; cvt.u32.u64 %0, t; }" : "=r"(a) : "l"(p));
    return a;
}

#define LDSM_X4(r0, r1, r2, r3, addr) \
    asm volatile("ldmatrix.sync.aligned.m8n8.x4.shared.b16 {%0,%1,%2,%3}, [%4];" \
        : "=r"(r0), "=r"(r1), "=r"(r2), "=r"(r3) : "r"(addr))

#define MMA_F16(c, a, b0, b1) \
    asm volatile("mma.sync.aligned.m16n8k16.row.col.f32.f16.f16.f32 " \
        "{%0,%1,%2,%3}, {%4,%5,%6,%7}, {%8,%9}, {%0,%1,%2,%3};" \
        : "+f"((c)[0]), "+f"((c)[1]), "+f"((c)[2]), "+f"((c)[3]) \
        : "r"((a)[0]), "r"((a)[1]), "r"((a)[2]), "r"((a)[3]), "r"(b0), "r"(b1))

#define CP_ASYNC16(dst, src) \
    asm volatile("cp.async.ca.shared.global [%0], [%1], 16;" :: "r"(dst), "l"(src))
#define CP_ASYNC16Z(dst, src, sz) \
    asm volatile("cp.async.ca.shared.global [%0], [%1], 16, %2;" :: "r"(dst), "l"(src), "r"(sz))
#define CP_COMMIT()  asm volatile("cp.async.commit_group;" ::: "memory")
#define CP_WAIT(n)   asm volatile("cp.async.wait_group %0;" :: "n"(n) : "memory")
#define CP_WAIT0()   asm volatile("cp.async.wait_group 0;" ::: "memory")

__device__ __forceinline__ uint32_t pack_h2(float v0, float v1) {
    __half2 h = __floats2half2_rn(v0, v1);
    return *reinterpret_cast<uint32_t*>(&h);
}

// ---------------------------------------------------------------------------
// GEMM0: h0 = fp16(x @ W_map + b_map).  A fp32 [M,500] staged via 3-deep
// cp.async ring; in-kernel smem fp32->fp16 conversion; Kpad=512, nchunk=16.
// CTA 128x128, 256 thr, 8 warps (4m x 2n of 32x64), 2 CTAs/SM.
// Stage: [A16 10240 | A32 16384 | B 10240] = 36864 B; 3 stages.
// ---------------------------------------------------------------------------
#define STG0_BYTES 36864
#define OFF0_A16 0
#define OFF0_A32 10240
#define OFF0_B   26624

__global__ void __launch_bounds__(256, 2)
k_mgemm0(const float* __restrict__ A1f, const __half* __restrict__ Bth,
         const float* __restrict__ bias, __half* __restrict__ Ch, int M)
{
    extern __shared__ char smem[];
    const uint32_t sb = s2u(smem);
    const int tid = threadIdx.x, wid = tid >> 5, lane = tid & 31;
    const int bm = blockIdx.x * 128;
    const int nchunk = 16, Kpad = 512;

    const int arow = tid >> 1;                 // 0..127
    const int ahalf = tid & 1;                 // k sub-half (16 elems)
    const uint32_t abase16 = (uint32_t)(arow * 80 + ahalf * 32);   // fp16 dest
    const uint32_t abase32 = (uint32_t)(arow * 128 + ahalf * 64);  // fp32 stage

    auto issueStage = [&](int kc) {
        const int s = kc % 3;
        const uint32_t st = sb + 1024 + s * STG0_BYTES;
        const int grow = bm + arow;
        const int gk = kc * 32 + ahalf * 16;
        const float* pa = A1f + (long)(grow < M ? grow : 0) * 500 + gk;
        uint32_t da = st + OFF0_A32 + abase32;
#pragma unroll
        for (int q = 0; q < 4; q++) {
            int sz = (grow < M && gk + q * 4 < 500) ? 16 : 0;
            CP_ASYNC16Z(da + q * 16, pa + q * 4, sz);
        }
        const __half* pb = Bth + (long)arow * Kpad + kc * 32 + ahalf * 16;
        uint32_t db = st + OFF0_B + abase16;
        CP_ASYNC16(db,      pb);
        CP_ASYNC16(db + 16, pb + 8);
        CP_COMMIT();
    };

    float c[2][8][4];
#pragma unroll
    for (int i = 0; i < 2; i++)
#pragma unroll
        for (int j = 0; j < 8; j++)
#pragma unroll
            for (int q = 0; q < 4; q++) c[i][j][q] = 0.f;

    const int wm = wid & 3;
    const int wn = (wid >> 2) * 64;
    const uint32_t aoff = (uint32_t)((wm * 32 + (lane & 15)) * 80 + (lane >> 4) * 16);
    const uint32_t boff = (uint32_t)((wn + ((lane >> 4) & 1) * 8 + (lane & 7)) * 80
                                     + ((lane >> 3) & 1) * 16);

    issueStage(0);
    issueStage(1);

    for (int kc = 0; kc < nchunk; ++kc) {
        const int s = kc % 3;
        const uint32_t st = sb + 1024 + s * STG0_BYTES;
        if (kc + 1 < nchunk) CP_WAIT(1); else CP_WAIT(0);
        __syncthreads();                         // stage s ready; stage (kc+2)%3 free
        if (kc + 2 < nchunk) issueStage(kc + 2);

        // convert own 64B fp32 -> 32B fp16 (in-stage)
        {
            const char* src = smem + 1024 + s * STG0_BYTES + OFF0_A32 + abase32;
            float4 f0 = *(const float4*)(src);
            float4 f1 = *(const float4*)(src + 16);
            float4 f2 = *(const float4*)(src + 32);
            float4 f3 = *(const float4*)(src + 48);
            char* dst = smem + 1024 + s * STG0_BYTES + OFF0_A16 + abase16;
            uint4 u;
            u.x = pack_h2(f0.x, f0.y); u.y = pack_h2(f0.z, f0.w);
            u.z = pack_h2(f1.x, f1.y); u.w = pack_h2(f1.z, f1.w);
            *(uint4*)(dst) = u;
            u.x = pack_h2(f2.x, f2.y); u.y = pack_h2(f2.z, f2.w);
            u.z = pack_h2(f3.x, f3.y); u.w = pack_h2(f3.z, f3.w);
            *(uint4*)(dst + 16) = u;
        }
        __syncthreads();                         // A16 visible to all warps

#pragma unroll
        for (int ks = 0; ks < 2; ks++) {
            uint32_t ah[2][4], bh[4][4];
#pragma unroll
            for (int mt = 0; mt < 2; mt++) {
                uint32_t aa = st + OFF0_A16 + aoff + mt * 16 * 80 + ks * 32;
                LDSM_X4(ah[mt][0], ah[mt][1], ah[mt][2], ah[mt][3], aa);
            }
#pragma unroll
            for (int nt = 0; nt < 4; nt++) {
                uint32_t ba = st + OFF0_B + boff + nt * 16 * 80 + ks * 32;
                LDSM_X4(bh[nt][0], bh[nt][1], bh[nt][2], bh[nt][3], ba);
            }
#pragma unroll
            for (int nt = 0; nt < 4; nt++)
#pragma unroll
                for (int mt = 0; mt < 2; mt++) {
                    MMA_F16(c[mt][nt * 2],     ah[mt], bh[nt][0], bh[nt][1]);
                    MMA_F16(c[mt][nt * 2 + 1], ah[mt], bh[nt][2], bh[nt][3]);
                }
        }
    }

    // ---- epilogue: fp16 out, bias, no relu ----
#pragma unroll
    for (int mt = 0; mt < 2; mt++) {
        int r0 = bm + wm * 32 + mt * 16 + (lane >> 2);
#pragma unroll
        for (int j = 0; j < 8; j++) {
            int col = wn + (j >> 1) * 16 + (j & 1) * 8 + (lane & 3) * 2;
            float b0 = bias[col], b1 = bias[col + 1];
#pragma unroll
            for (int h = 0; h < 2; h++) {
                int row = r0 + h * 8;
                if (row >= M) continue;
                *(uint32_t*)(Ch + (long)row * 128 + col) =
                    pack_h2(c[mt][j][h * 2 + 0] + b0, c[mt][j][h * 2 + 1] + b1);
            }
        }
    }
}

// ---------------------------------------------------------------------------
// GEMM (layers 1-3): pure fp16, 2-stage cp.async (R14-proven structure).
//   MODE 1: A = [A1h|A2h] concat, each [M,128], Kpad=256
//   MODE 2: A = A1h [M,Kpad]
// ---------------------------------------------------------------------------
#define STG_BYTES 20480
#define OFF_AH 0
#define OFF_BH 10240

template<int MODE, bool RELU, bool BIAS, bool HOUT>
__global__ void __launch_bounds__(256, 2)
k_mgemm(const __half* __restrict__ A1h, const __half* __restrict__ A2h,
        const __half* __restrict__ Bth,
        int Kpad, int nchunk, const float* __restrict__ bias,
        float* __restrict__ Cf, __half* __restrict__ Ch, int M, int Nout)
{
    extern __shared__ char smem[];
    const uint32_t sb = s2u(smem);
    const int tid = threadIdx.x, wid = tid >> 5, lane = tid & 31;
    const int bm = blockIdx.x * 128;
    const int n0 = blockIdx.y * 128;

    const int arow = tid >> 1;
    const int ahalf = tid & 1;
    const uint32_t abase = (uint32_t)(arow * 80 + ahalf * 32);

    auto cpasyncA = [&](int kc, int s) {
        const int gk = kc * 32 + ahalf * 16;
        const uint32_t st = sb + 1024 + s * STG_BYTES;
        const int grow = bm + arow;
        const int sz = (grow < M) ? 16 : 0;
        const int r = (grow < M) ? grow : 0;
        const __half* ph;
        if (MODE == 1) {
            if (gk < 128) ph = A1h + (long)r * 128 + gk;
            else          ph = A2h + (long)r * 128 + (gk - 128);
        } else {
            ph = A1h + (long)r * Kpad + gk;
        }
        uint32_t dh = st + OFF_AH + abase;
        CP_ASYNC16Z(dh,      ph,     sz);
        CP_ASYNC16Z(dh + 16, ph + 8, sz);
    };
    auto cpasyncB = [&](int kc, int s) {
        const int k0 = kc * 32;
        const uint32_t st = sb + 1024 + s * STG_BYTES;
        const __half* ph = Bth + (long)(n0 + arow) * Kpad + k0 + ahalf * 16;
        uint32_t dh = st + OFF_BH + abase;
        CP_ASYNC16(dh,      ph);
        CP_ASYNC16(dh + 16, ph + 8);
    };

    float c[2][8][4];
#pragma unroll
    for (int i = 0; i < 2; i++)
#pragma unroll
        for (int j = 0; j < 8; j++)
#pragma unroll
            for (int q = 0; q < 4; q++) c[i][j][q] = 0.f;

    const int wm = wid & 3;
    const int wn = (wid >> 2) * 64;
    const uint32_t aoff = (uint32_t)((wm * 32 + (lane & 15)) * 80 + (lane >> 4) * 16);
    const uint32_t boff = (uint32_t)((wn + ((lane >> 4) & 1) * 8 + (lane & 7)) * 80
                                     + ((lane >> 3) & 1) * 16);

    auto compute = [&](int s) {
        const uint32_t stb = sb + 1024 + s * STG_BYTES;
#pragma unroll
        for (int ks = 0; ks < 2; ks++) {
            uint32_t ah[2][4], bh[4][4];
#pragma unroll
            for (int mt = 0; mt < 2; mt++) {
                uint32_t aa = stb + aoff + mt * 16 * 80 + ks * 32;
                LDSM_X4(ah[mt][0], ah[mt][1], ah[mt][2], ah[mt][3], aa + OFF_AH);
            }
#pragma unroll
            for (int nt = 0; nt < 4; nt++) {
                uint32_t ba = stb + boff + nt * 16 * 80 + ks * 32;
                LDSM_X4(bh[nt][0], bh[nt][1], bh[nt][2], bh[nt][3], ba + OFF_BH);
            }
#pragma unroll
            for (int nt = 0; nt < 4; nt++)
#pragma unroll
                for (int mt = 0; mt < 2; mt++) {
                    MMA_F16(c[mt][nt * 2],     ah[mt], bh[nt][0], bh[nt][1]);
                    MMA_F16(c[mt][nt * 2 + 1], ah[mt], bh[nt][2], bh[nt][3]);
                }
        }
    };

    cpasyncA(0, 0); cpasyncB(0, 0); CP_COMMIT();
    CP_WAIT0();
    __syncthreads();
    for (int kc = 0; kc < nchunk; ++kc) {
        const int s = kc & 1;
        if (kc + 1 < nchunk) { cpasyncA(kc + 1, s ^ 1); cpasyncB(kc + 1, s ^ 1); CP_COMMIT(); }
        compute(s);
        if (kc + 1 < nchunk) { CP_WAIT0(); __syncthreads(); }
    }

    // ---- epilogue ----
#pragma unroll
    for (int mt = 0; mt < 2; mt++) {
        int r0 = bm + wm * 32 + mt * 16 + (lane >> 2);
#pragma unroll
        for (int j = 0; j < 8; j++) {
            int cb = wn + (j >> 1) * 16 + (j & 1) * 8 + (lane & 3) * 2;
            int col = n0 + cb;
            if (col >= Nout) continue;
            float b0 = BIAS ? bias[col] : 0.f;
            float b1 = BIAS ? bias[col + 1] : 0.f;
#pragma unroll
            for (int h = 0; h < 2; h++) {
                int row = r0 + h * 8;
                if (row >= M) continue;
                float v0 = c[mt][j][h * 2 + 0] + b0;
                float v1 = c[mt][j][h * 2 + 1] + b1;
                if (RELU) { v0 = fmaxf(v0, 0.f); v1 = fmaxf(v1, 0.f); }
                if (HOUT)
                    *(uint32_t*)(Ch + (long)row * Nout + col) = pack_h2(v0, v1);
                else
                    *(float2*)(Cf + (long)row * Nout + col) = make_float2(v0, v1);
            }
        }
    }
}

// ---------------------------------------------------------------------------
// Weight prep: fp16
// ---------------------------------------------------------------------------
__global__ void k_prep_map(const float* __restrict__ W, __half* __restrict__ Bh)
{
    int i = blockIdx.x * blockDim.x + threadIdx.x;
    if (i >= 128 * 512) return;
    int n = i >> 9, k = i & 511;
    float w = (k < 500) ? W[k * 128 + n] : 0.f;
    Bh[i] = __float2half_rn(w);
}

__global__ void k_prep_cat(const float* __restrict__ Wr, const float* __restrict__ Wl,
                           int N, __half* __restrict__ Bh)
{
    int i = blockIdx.x * blockDim.x + threadIdx.x;
    if (i >= N * 256) return;
    int n = i >> 8, k = i & 255;
    float w = (k < 128) ? Wr[k * N + n] : Wl[(k - 128) * N + n];
    Bh[i] = __float2half_rn(w);
}

__global__ void k_prep_l3(const float* __restrict__ Wl3, const float* __restrict__ Wr3,
                          __half* __restrict__ Bh)
{
    int i = blockIdx.x * blockDim.x + threadIdx.x;
    if (i >= 128 * 256) return;
    int n = i >> 8, k = i & 255;
    float w = 0.f;
    if (n < 40)      w = Wl3[k * 40 + n];
    else if (n < 80) w = Wr3[k * 40 + (n - 40)];
    Bh[i] = __float2half_rn(w);
}

// ---------------------------------------------------------------------------
// CSR build
// ---------------------------------------------------------------------------
__global__ void k_hist(const int* __restrict__ ei, int E, int* __restrict__ deg)
{
    int e = blockIdx.x * blockDim.x + threadIdx.x;
    if (e < E) atomicAdd(&deg[ei[E + e]], 1);
}

__global__ void __launch_bounds__(1024, 1)
k_scan(const int* __restrict__ deg, int* __restrict__ rowptr, int n)
{
    __shared__ int sh[32];
    __shared__ int carry;
    if (threadIdx.x == 0) carry = 0;
    __syncthreads();
    const int lane = threadIdx.x & 31, w = threadIdx.x >> 5;
    for (int base = 0; base < n; base += 1024) {
        int i = base + threadIdx.x;
        int v = (i < n) ? deg[i] : 0;
        int x = v;
#pragma unroll
        for (int o = 1; o < 32; o <<= 1) {
            int y = __shfl_up_sync(0xffffffffu, x, o);
            if (lane >= o) x += y;
        }
        if (lane == 31) sh[w] = x;
        __syncthreads();
        if (w == 0) {
            int s = sh[lane];
#pragma unroll
            for (int o = 1; o < 32; o <<= 1) {
                int y = __shfl_up_sync(0xffffffffu, s, o);
                if (lane >= o) s += y;
            }
            sh[lane] = s;
        }
        __syncthreads();
        int incl = x + (w ? sh[w - 1] : 0);
        if (i < n) rowptr[i] = carry + incl - v;
        __syncthreads();
        if (threadIdx.x == 0) carry += sh[31];
        __syncthreads();
    }
    if (threadIdx.x == 0) rowptr[n] = carry;
}

__global__ void k_fill(const int* __restrict__ ei, int E,
                       int* __restrict__ cursor, int* __restrict__ csr)
{
    int e = blockIdx.x * blockDim.x + threadIdx.x;
    if (e >= E) return;
    int s = ei[e], d = ei[E + e];
    int pos = atomicAdd(&cursor[d], 1);
    csr[pos] = s;
}

// ---------------------------------------------------------------------------
// fp16 CSR mean-aggregation (stride 128 halfs)
// ---------------------------------------------------------------------------
__device__ __forceinline__ void acc_h8(float* a, uint4 v) {
    const __half2* p = reinterpret_cast<const __half2*>(&v);
#pragma unroll
    for (int i = 0; i < 4; i++) {
        float2 f = __half22float2(p[i]);
        a[2 * i]     += f.x;
        a[2 * i + 1] += f.y;
    }
}

__global__ void k_agg_h(const int* __restrict__ rowptr, const int* __restrict__ csr,
                        const __half* __restrict__ src, __half* __restrict__ dst, int Nn)
{
    long t = (long)blockIdx.x * blockDim.x + threadIdx.x;
    if (t >= (long)Nn * 16) return;
    int node = (int)(t >> 4);
    int c8   = (int)(t & 15) * 8;
    int b  = rowptr[node];
    int e2 = rowptr[node + 1];
    float a0[8] = {0, 0, 0, 0, 0, 0, 0, 0};
    float a1[8] = {0, 0, 0, 0, 0, 0, 0, 0};
    int j = b;
    for (; j + 2 <= e2; j += 2) {
        uint4 v0 = *(const uint4*)(src + (long)csr[j]     * 128 + c8);
        uint4 v1 = *(const uint4*)(src + (long)csr[j + 1] * 128 + c8);
        acc_h8(a0, v0);
        acc_h8(a1, v1);
    }
    if (j < e2) {
        uint4 v0 = *(const uint4*)(src + (long)csr[j] * 128 + c8);
        acc_h8(a0, v0);
    }
    float inv = 1.0f / fmaxf((float)(e2 - b), 1.0f);
    uint4 o;
    o.x = pack_h2((a0[0] + a1[0]) * inv, (a0[1] + a1[1]) * inv);
    o.y = pack_h2((a0[2] + a1[2]) * inv, (a0[3] + a1[3]) * inv);
    o.z = pack_h2((a0[4] + a1[4]) * inv, (a0[5] + a1[5]) * inv);
    o.w = pack_h2((a0[6] + a1[6]) * inv, (a0[7] + a1[7]) * inv);
    *(uint4*)(dst + (long)node * 128 + c8) = o;
}

// ---------------------------------------------------------------------------
// fp32 CSR mean-aggregation (layer 3): t3r3[80] -> agg[40]
// ---------------------------------------------------------------------------
__global__ void k_agg_f(const int* __restrict__ rowptr, const int* __restrict__ csr,
                        const float* __restrict__ src, float* __restrict__ dst, int Nn)
{
    long t = (long)blockIdx.x * blockDim.x + threadIdx.x;
    if (t >= (long)Nn * 10) return;
    int node = (int)(t / 10);
    int c4   = (int)(t - (long)node * 10) * 4;
    int b  = rowptr[node];
    int e2 = rowptr[node + 1];
    float4 a0 = make_float4(0.f, 0.f, 0.f, 0.f);
    float4 a1 = make_float4(0.f, 0.f, 0.f, 0.f);
    int j = b;
    for (; j + 2 <= e2; j += 2) {
        float4 v0 = *(const float4*)(src + (long)csr[j]     * 80 + c4);
        float4 v1 = *(const float4*)(src + (long)csr[j + 1] * 80 + c4);
        a0.x += v0.x; a0.y += v0.y; a0.z += v0.z; a0.w += v0.w;
        a1.x += v1.x; a1.y += v1.y; a1.z += v1.z; a1.w += v1.w;
    }
    if (j < e2) {
        float4 v0 = *(const float4*)(src + (long)csr[j] * 80 + c4);
        a0.x += v0.x; a0.y += v0.y; a0.z += v0.z; a0.w += v0.w;
    }
    float inv = 1.0f / fmaxf((float)(e2 - b), 1.0f);
    float4 acc;
    acc.x = (a0.x + a1.x) * inv;
    acc.y = (a0.y + a1.y) * inv;
    acc.z = (a0.z + a1.z) * inv;
    acc.w = (a0.w + a1.w) * inv;
    *(float4*)(dst + (long)node * 40 + c4) = acc;
}

// ---------------------------------------------------------------------------
// Final log_softmax
// ---------------------------------------------------------------------------
__global__ void k_final(const float* __restrict__ agg, const float* __restrict__ t3r3,
                        const float* __restrict__ bias, float* __restrict__ out, int Nn)
{
    int gw   = (int)((blockIdx.x * (long)blockDim.x + threadIdx.x) >> 5);
    int lane = threadIdx.x & 31;
    if (gw >= Nn) return;

    const float* ar = agg  + (long)gw * 40;
    const float* rr = t3r3 + (long)gw * 80 + 40;

    float x0 = ar[lane] + bias[lane] + rr[lane];
    float x1 = -3.402823466e38f;
    if (lane < 8) x1 = ar[32 + lane] + bias[32 + lane] + rr[32 + lane];

    float m = fmaxf(x0, x1);
#pragma unroll
    for (int o = 16; o; o >>= 1) m = fmaxf(m, __shfl_xor_sync(0xffffffffu, m, o));

    float s = expf(x0 - m) + ((lane < 8) ? expf(x1 - m) : 0.0f);
#pragma unroll
    for (int o = 16; o; o >>= 1) s += __shfl_xor_sync(0xffffffffu, s, o);

    float lse = m + logf(s);
    out[(long)gw * 40 + lane] = x0 - lse;
    if (lane < 8) out[(long)gw * 40 + 32 + lane] = x1 - lse;
}

// ---------------------------------------------------------------------------
// Host launcher. GEMM0 at launch position 5 (ncu profiles 5th launch).
// ---------------------------------------------------------------------------
extern "C" void kernel_launch(void* const* d_in, const int* in_sizes, int n_in,
                              void* d_out, int out_size)
{
    const float* x     = (const float*)d_in[0];
    const int*   ei    = (const int*)  d_in[1];
    const float* W_map = (const float*)d_in[2];
    const float* b_map = (const float*)d_in[3];
    const float* Wl1   = (const float*)d_in[4];
    const float* bl1   = (const float*)d_in[5];
    const float* Wr1   = (const float*)d_in[6];
    const float* Wl2   = (const float*)d_in[7];
    const float* bl2   = (const float*)d_in[8];
    const float* Wr2   = (const float*)d_in[9];
    const float* Wl3   = (const float*)d_in[10];
    const float* bl3   = (const float*)d_in[11];
    const float* Wr3   = (const float*)d_in[12];
    float* out = (float*)d_out;

    const int E  = in_sizes[1] / 2;
    const int Nn = NN;

    void *p_h0, *p_h1, *p_h2, *p_aggh, *p_agg, *p_t3r3;
    void *p_deg, *p_rowptr, *p_cursor, *p_csr;
    void *p_b0h, *p_b1h, *p_b2h, *p_b3h;
    cudaGetSymbolAddress(&p_h0,   g_h0);
    cudaGetSymbolAddress(&p_h1,   g_h1);
    cudaGetSymbolAddress(&p_h2,   g_h2);
    cudaGetSymbolAddress(&p_aggh, g_aggh);
    cudaGetSymbolAddress(&p_agg,  g_agg);
    cudaGetSymbolAddress(&p_t3r3, g_t3r3);
    cudaGetSymbolAddress(&p_deg,    g_deg);
    cudaGetSymbolAddress(&p_rowptr, g_rowptr);
    cudaGetSymbolAddress(&p_cursor, g_cursor);
    cudaGetSymbolAddress(&p_csr,    g_csr);
    cudaGetSymbolAddress(&p_b0h, g_B0h);
    cudaGetSymbolAddress(&p_b1h, g_B1h);
    cudaGetSymbolAddress(&p_b2h, g_B2h);
    cudaGetSymbolAddress(&p_b3h, g_B3h);

    __half* h0   = (__half*)p_h0;
    __half* h1   = (__half*)p_h1;
    __half* h2   = (__half*)p_h2;
    __half* aggh = (__half*)p_aggh;
    float*  agg  = (float*)p_agg;
    float*  t3r3 = (float*)p_t3r3;
    int* deg    = (int*)p_deg;
    int* rowptr = (int*)p_rowptr;
    int* cursor = (int*)p_cursor;
    int* csr    = (int*)p_csr;

    const int SMEM0 = 1024 + 3 * STG0_BYTES;   // 111616
    const int SMEM  = 1024 + 2 * STG_BYTES;    // 41984
    cudaFuncSetAttribute(k_mgemm0, cudaFuncAttributeMaxDynamicSharedMemorySize, SMEM0);
    cudaFuncSetAttribute(k_mgemm<1, true,  true,  true>,  cudaFuncAttributeMaxDynamicSharedMemorySize, SMEM);
    cudaFuncSetAttribute(k_mgemm<2, false, false, false>, cudaFuncAttributeMaxDynamicSharedMemorySize, SMEM);

    const int MT = (Nn + 127) / 128;   // 391 M-tiles
    dim3 g1(MT, 1), g2(MT, 2);

    // Launches 1-4: memset + prep (GEMM0 needs only prep_map)
    cudaMemsetAsync(p_deg, 0, (size_t)Nn * sizeof(int));                                   // 1
    k_prep_map<<<(128 * 512 + 255) / 256, 256>>>(W_map, (__half*)p_b0h);                   // 2
    k_prep_cat<<<(128 * 256 + 255) / 256, 256>>>(Wr1, Wl1, 128, (__half*)p_b1h);           // 3
    k_prep_cat<<<(256 * 256 + 255) / 256, 256>>>(Wr2, Wl2, 256, (__half*)p_b2h);           // 4

    // Launch 5 (PROFILED): h0 = fp16(x @ W_map + b_map), cp.async-piped fp32 A
    k_mgemm0<<<MT, 256, SMEM0>>>(x, (__half*)p_b0h, b_map, h0, Nn);

    // Remaining prep + CSR build
    k_prep_l3 <<<(128 * 256 + 255) / 256, 256>>>(Wl3, Wr3, (__half*)p_b3h);
    k_hist<<<(E + 255) / 256, 256>>>(ei, E, deg);
    k_scan<<<1, 1024>>>(deg, rowptr, Nn);
    cudaMemcpyAsync(cursor, rowptr, (size_t)Nn * sizeof(int), cudaMemcpyDeviceToDevice);
    k_fill<<<(E + 255) / 256, 256>>>(ei, E, cursor, csr);

    // layer 1
    k_agg_h<<<(int)(((long)Nn * 16 + 255) / 256), 256>>>(rowptr, csr, h0, aggh, Nn);
    k_mgemm<1, true, true, true><<<g1, 256, SMEM>>>(
        h0, aggh, (__half*)p_b1h, 256, 8, bl1, nullptr, h1, Nn, 128);

    // layer 2
    k_agg_h<<<(int)(((long)Nn * 16 + 255) / 256), 256>>>(rowptr, csr, h1, aggh, Nn);
    k_mgemm<1, true, true, true><<<g2, 256, SMEM>>>(
        h1, aggh, (__half*)p_b2h, 256, 8, bl2, nullptr, h2, Nn, 256);

    // layer 3: transform-then-aggregate
    k_mgemm<2, false, false, false><<<g1, 256, SMEM>>>(
        h2, nullptr, (__half*)p_b3h, 256, 8, nullptr, t3r3, nullptr, Nn, 80);
    k_agg_f<<<(int)(((long)Nn * 10 + 255) / 256), 256>>>(rowptr, csr, t3r3, agg, Nn);

    k_final<<<(Nn * 32 + 255) / 256, 256>>>(agg, t3r3, bl3, out, Nn);
}

// round 17
// speedup vs baseline: 1.3149x; 1.3149x over previous
#include <cuda_runtime.h>
#include <cuda_fp16.h>
#include <cstdint>

// Problem constants
#define NN      50000
#define EDGES   800000
#define F_IN    500

// ---------------------------------------------------------------------------
// Device scratch
// ---------------------------------------------------------------------------
__device__ __half g_h0[NN * 128];
__device__ __half g_h1[NN * 128];
__device__ __half g_h2[NN * 256];
__device__ __half g_aggh[NN * 128];
__device__ float  g_t3r3[NN * 80];

__device__ int g_deg[NN];
__device__ int g_rowptr[NN + 1];
__device__ int g_cursor[NN];
__device__ int g_csr[EDGES];

// Weights: Bt[n][k] (K-major, transposed), fp16
__device__ __half g_B0h[128 * 512];
__device__ __half g_B1h[128 * 256];
__device__ __half g_B2h[256 * 256];
__device__ __half g_B3h[128 * 256];

// ---------------------------------------------------------------------------
// PTX helpers
// ---------------------------------------------------------------------------
__device__ __forceinline__ uint32_t s2u(const void* p) {
    uint32_t a;
    asm("{ .reg .u64 t; cvta.to.shared.u64 t, %1; cvt.u32.u64 %0, t; }" : "=r"(a) : "l"(p));
    return a;
}

#define LDSM_X4(r0, r1, r2, r3, addr) \
    asm volatile("ldmatrix.sync.aligned.m8n8.x4.shared.b16 {%0,%1,%2,%3}, [%4];" \
        : "=r"(r0), "=r"(r1), "=r"(r2), "=r"(r3) : "r"(addr))

#define MMA_F16(c, a, b0, b1) \
    asm volatile("mma.sync.aligned.m16n8k16.row.col.f32.f16.f16.f32 " \
        "{%0,%1,%2,%3}, {%4,%5,%6,%7}, {%8,%9}, {%0,%1,%2,%3};" \
        : "+f"((c)[0]), "+f"((c)[1]), "+f"((c)[2]), "+f"((c)[3]) \
        : "r"((a)[0]), "r"((a)[1]), "r"((a)[2]), "r"((a)[3]), "r"(b0), "r"(b1))

#define CP_ASYNC16(dst, src) \
    asm volatile("cp.async.ca.shared.global [%0], [%1], 16;" :: "r"(dst), "l"(src))
#define CP_ASYNC16Z(dst, src, sz) \
    asm volatile("cp.async.ca.shared.global [%0], [%1], 16, %2;" :: "r"(dst), "l"(src), "r"(sz))
#define CP_COMMIT()  asm volatile("cp.async.commit_group;" ::: "memory")
#define CP_WAIT0()   asm volatile("cp.async.wait_group 0;" ::: "memory")

__device__ __forceinline__ uint32_t pack_h2(float v0, float v1) {
    __half2 h = __floats2half2_rn(v0, v1);
    return *reinterpret_cast<uint32_t*>(&h);
}

// ---------------------------------------------------------------------------
// Tensor-core GEMM: pure fp16 (fp32 accumulate). R14-proven structure.
//   MODE 0: A fp32 [M,500], Kpad=512 (LDG+cvt+STS path)
//   MODE 1: A = [A1h|A2h] fp16, each [M,128], Kpad=256 (pure cp.async)
//   MODE 2: A = A1h fp16 [M,Kpad] (pure cp.async)
// CTA 128x128, BK=32, 256 thr, 8 warps (4m x 2n of 32x64), 2 CTAs/SM.
// ---------------------------------------------------------------------------
#define STG_BYTES 20480
#define OFF_AH 0
#define OFF_BH 10240

template<int MODE, bool RELU, bool BIAS, bool HOUT>
__global__ void __launch_bounds__(256, 2)
k_mgemm(const float* __restrict__ A1f,
        const __half* __restrict__ A1h, const __half* __restrict__ A2h,
        const __half* __restrict__ Bth,
        int Kpad, int nchunk, const float* __restrict__ bias,
        float* __restrict__ Cf, __half* __restrict__ Ch, int M, int Nout)
{
    extern __shared__ char smem[];
    const uint32_t sb = s2u(smem);
    const int tid = threadIdx.x, wid = tid >> 5, lane = tid & 31;
    const int bm = blockIdx.x * 128;
    const int n0 = blockIdx.y * 128;

    const int arow = tid >> 1;                 // 0..127
    const int ahalf = tid & 1;                 // k sub-half (16 elems)
    const uint32_t abase = (uint32_t)(arow * 80 + ahalf * 32);

    float av[16];

    auto prefetchA = [&](int kc) {             // MODE 0 only
        const int k0 = kc * 32;
        const int grow = bm + arow;
#pragma unroll
        for (int q = 0; q < 4; q++) {
            int gk = k0 + ahalf * 16 + q * 4;
            float4 v = make_float4(0.f, 0.f, 0.f, 0.f);
            if (grow < M && gk + 3 < 500) v = *(const float4*)(A1f + (long)grow * 500 + gk);
            av[q * 4 + 0] = v.x; av[q * 4 + 1] = v.y;
            av[q * 4 + 2] = v.z; av[q * 4 + 3] = v.w;
        }
    };
    auto storeStageA = [&](int s) {            // MODE 0 only
        char* st = smem + 1024 + s * STG_BYTES;
        uint4 u;
        u.x = pack_h2(av[0],  av[1]);  u.y = pack_h2(av[2],  av[3]);
        u.z = pack_h2(av[4],  av[5]);  u.w = pack_h2(av[6],  av[7]);
        *(uint4*)(st + OFF_AH + abase) = u;
        u.x = pack_h2(av[8],  av[9]);  u.y = pack_h2(av[10], av[11]);
        u.z = pack_h2(av[12], av[13]); u.w = pack_h2(av[14], av[15]);
        *(uint4*)(st + OFF_AH + abase + 16) = u;
    };
    auto cpasyncA = [&](int kc, int s) {       // MODE 1/2 only
        const int gk = kc * 32 + ahalf * 16;
        const uint32_t st = sb + 1024 + s * STG_BYTES;
        const int grow = bm + arow;
        const int sz = (grow < M) ? 16 : 0;
        const int r = (grow < M) ? grow : 0;
        const __half* ph;
        if (MODE == 1) {
            if (gk < 128) ph = A1h + (long)r * 128 + gk;
            else          ph = A2h + (long)r * 128 + (gk - 128);
        } else {
            ph = A1h + (long)r * Kpad + gk;
        }
        uint32_t dh = st + OFF_AH + abase;
        CP_ASYNC16Z(dh,      ph,     sz);
        CP_ASYNC16Z(dh + 16, ph + 8, sz);
    };
    auto cpasyncB = [&](int kc, int s) {
        const int k0 = kc * 32;
        const uint32_t st = sb + 1024 + s * STG_BYTES;
        const __half* ph = Bth + (long)(n0 + arow) * Kpad + k0 + ahalf * 16;
        uint32_t dh = st + OFF_BH + abase;
        CP_ASYNC16(dh,      ph);
        CP_ASYNC16(dh + 16, ph + 8);
    };

    float c[2][8][4];
#pragma unroll
    for (int i = 0; i < 2; i++)
#pragma unroll
        for (int j = 0; j < 8; j++)
#pragma unroll
            for (int q = 0; q < 4; q++) c[i][j][q] = 0.f;

    const int wm = wid & 3;
    const int wn = (wid >> 2) * 64;
    const uint32_t aoff = (uint32_t)((wm * 32 + (lane & 15)) * 80 + (lane >> 4) * 16);
    const uint32_t boff = (uint32_t)((wn + ((lane >> 4) & 1) * 8 + (lane & 7)) * 80
                                     + ((lane >> 3) & 1) * 16);

    auto compute = [&](int s) {
        const uint32_t stb = sb + 1024 + s * STG_BYTES;
#pragma unroll
        for (int ks = 0; ks < 2; ks++) {
            uint32_t ah[2][4], bh[4][4];
#pragma unroll
            for (int mt = 0; mt < 2; mt++) {
                uint32_t aa = stb + aoff + mt * 16 * 80 + ks * 32;
                LDSM_X4(ah[mt][0], ah[mt][1], ah[mt][2], ah[mt][3], aa + OFF_AH);
            }
#pragma unroll
            for (int nt = 0; nt < 4; nt++) {
                uint32_t ba = stb + boff + nt * 16 * 80 + ks * 32;
                LDSM_X4(bh[nt][0], bh[nt][1], bh[nt][2], bh[nt][3], ba + OFF_BH);
            }
#pragma unroll
            for (int nt = 0; nt < 4; nt++)
#pragma unroll
                for (int mt = 0; mt < 2; mt++) {
                    MMA_F16(c[mt][nt * 2],     ah[mt], bh[nt][0], bh[nt][1]);
                    MMA_F16(c[mt][nt * 2 + 1], ah[mt], bh[nt][2], bh[nt][3]);
                }
        }
    };

    if (MODE == 0) {
        prefetchA(0);
        cpasyncB(0, 0); CP_COMMIT();
        storeStageA(0);
        CP_WAIT0();
        for (int kc = 0; kc < nchunk; ++kc) {
            const int s = kc & 1;
            if (kc + 1 < nchunk) prefetchA(kc + 1);
            __syncthreads();
            if (kc + 1 < nchunk) { cpasyncB(kc + 1, s ^ 1); CP_COMMIT(); }
            compute(s);
            if (kc + 1 < nchunk) { storeStageA(s ^ 1); CP_WAIT0(); }
        }
    } else {
        cpasyncA(0, 0); cpasyncB(0, 0); CP_COMMIT();
        CP_WAIT0();
        __syncthreads();
        for (int kc = 0; kc < nchunk; ++kc) {
            const int s = kc & 1;
            if (kc + 1 < nchunk) { cpasyncA(kc + 1, s ^ 1); cpasyncB(kc + 1, s ^ 1); CP_COMMIT(); }
            compute(s);
            if (kc + 1 < nchunk) { CP_WAIT0(); __syncthreads(); }
        }
    }

    // ---- epilogue ----
#pragma unroll
    for (int mt = 0; mt < 2; mt++) {
        int r0 = bm + wm * 32 + mt * 16 + (lane >> 2);
#pragma unroll
        for (int j = 0; j < 8; j++) {
            int cb = wn + (j >> 1) * 16 + (j & 1) * 8 + (lane & 3) * 2;
            int col = n0 + cb;
            if (col >= Nout) continue;
            float b0 = BIAS ? bias[col] : 0.f;
            float b1 = BIAS ? bias[col + 1] : 0.f;
#pragma unroll
            for (int h = 0; h < 2; h++) {
                int row = r0 + h * 8;
                if (row >= M) continue;
                float v0 = c[mt][j][h * 2 + 0] + b0;
                float v1 = c[mt][j][h * 2 + 1] + b1;
                if (RELU) { v0 = fmaxf(v0, 0.f); v1 = fmaxf(v1, 0.f); }
                if (HOUT)
                    *(uint32_t*)(Ch + (long)row * Nout + col) = pack_h2(v0, v1);
                else
                    *(float2*)(Cf + (long)row * Nout + col) = make_float2(v0, v1);
            }
        }
    }
}

// ---------------------------------------------------------------------------
// Merged weight prep (one kernel, range-dispatched): fp16 K-major transposes
//   [0, 65536)        B0: W_map [500,128] -> [128][512]
//   [65536, 98304)    B1: [Wr1;Wl1] -> [128][256]
//   [98304, 163840)   B2: [Wr2;Wl2] -> [256][256]
//   [163840, 196608)  B3: [Wl3|Wr3] pad N->128 -> [128][256]
// ---------------------------------------------------------------------------
__global__ void k_prep_all(const float* __restrict__ W_map,
                           const float* __restrict__ Wr1, const float* __restrict__ Wl1,
                           const float* __restrict__ Wr2, const float* __restrict__ Wl2,
                           const float* __restrict__ Wl3, const float* __restrict__ Wr3,
                           __half* __restrict__ B0, __half* __restrict__ B1,
                           __half* __restrict__ B2, __half* __restrict__ B3)
{
    int i = blockIdx.x * blockDim.x + threadIdx.x;
    if (i < 65536) {
        int n = i >> 9, k = i & 511;
        float w = (k < 500) ? W_map[k * 128 + n] : 0.f;
        B0[i] = __float2half_rn(w);
    } else if (i < 98304) {
        int j = i - 65536;
        int n = j >> 8, k = j & 255;
        float w = (k < 128) ? Wr1[k * 128 + n] : Wl1[(k - 128) * 128 + n];
        B1[j] = __float2half_rn(w);
    } else if (i < 163840) {
        int j = i - 98304;
        int n = j >> 8, k = j & 255;
        float w = (k < 128) ? Wr2[k * 256 + n] : Wl2[(k - 128) * 256 + n];
        B2[j] = __float2half_rn(w);
    } else if (i < 196608) {
        int j = i - 163840;
        int n = j >> 8, k = j & 255;
        float w = 0.f;
        if (n < 40)      w = Wl3[k * 40 + n];
        else if (n < 80) w = Wr3[k * 40 + (n - 40)];
        B3[j] = __float2half_rn(w);
    }
}

// ---------------------------------------------------------------------------
// CSR build
// ---------------------------------------------------------------------------
__global__ void k_hist(const int* __restrict__ ei, int E, int* __restrict__ deg)
{
    int e = blockIdx.x * blockDim.x + threadIdx.x;
    if (e < E) atomicAdd(&deg[ei[E + e]], 1);
}

// 4-elements/thread single-block scan: 13 iterations over 50000 (4096/iter)
__global__ void __launch_bounds__(1024, 1)
k_scan(const int* __restrict__ deg, int* __restrict__ rowptr, int n)
{
    __shared__ int sh[32];
    __shared__ int carry;
    if (threadIdx.x == 0) carry = 0;
    __syncthreads();
    const int lane = threadIdx.x & 31, w = threadIdx.x >> 5;
    for (int base = 0; base < n; base += 4096) {
        int i = base + threadIdx.x * 4;
        int4 v = make_int4(0, 0, 0, 0);
        if (i < n) v = *(const int4*)(deg + i);          // n % 4 == 0
        int t = v.x + v.y + v.z + v.w;
        int x = t;
#pragma unroll
        for (int o = 1; o < 32; o <<= 1) {
            int y = __shfl_up_sync(0xffffffffu, x, o);
            if (lane >= o) x += y;
        }
        if (lane == 31) sh[w] = x;
        __syncthreads();
        if (w == 0) {
            int s = sh[lane];
#pragma unroll
            for (int o = 1; o < 32; o <<= 1) {
                int y = __shfl_up_sync(0xffffffffu, s, o);
                if (lane >= o) s += y;
            }
            sh[lane] = s;
        }
        __syncthreads();
        int pre = carry + (w ? sh[w - 1] : 0) + x - t;   // exclusive before thread
        if (i < n) {
            int4 o;
            o.x = pre;
            o.y = pre + v.x;
            o.z = pre + v.x + v.y;
            o.w = pre + v.x + v.y + v.z;
            *(int4*)(rowptr + i) = o;
        }
        __syncthreads();
        if (threadIdx.x == 0) carry += sh[31];
        __syncthreads();
    }
    if (threadIdx.x == 0) rowptr[n] = carry;
}

__global__ void k_fill(const int* __restrict__ ei, int E,
                       int* __restrict__ cursor, int* __restrict__ csr)
{
    int e = blockIdx.x * blockDim.x + threadIdx.x;
    if (e >= E) return;
    int s = ei[e], d = ei[E + e];
    int pos = atomicAdd(&cursor[d], 1);
    csr[pos] = s;
}

// ---------------------------------------------------------------------------
// fp16 CSR mean-aggregation (stride 128 halfs)
// ---------------------------------------------------------------------------
__device__ __forceinline__ void acc_h8(float* a, uint4 v) {
    const __half2* p = reinterpret_cast<const __half2*>(&v);
#pragma unroll
    for (int i = 0; i < 4; i++) {
        float2 f = __half22float2(p[i]);
        a[2 * i]     += f.x;
        a[2 * i + 1] += f.y;
    }
}

__global__ void k_agg_h(const int* __restrict__ rowptr, const int* __restrict__ csr,
                        const __half* __restrict__ src, __half* __restrict__ dst, int Nn)
{
    long t = (long)blockIdx.x * blockDim.x + threadIdx.x;
    if (t >= (long)Nn * 16) return;
    int node = (int)(t >> 4);
    int c8   = (int)(t & 15) * 8;
    int b  = rowptr[node];
    int e2 = rowptr[node + 1];
    float a0[8] = {0, 0, 0, 0, 0, 0, 0, 0};
    float a1[8] = {0, 0, 0, 0, 0, 0, 0, 0};
    int j = b;
    for (; j + 2 <= e2; j += 2) {
        uint4 v0 = *(const uint4*)(src + (long)csr[j]     * 128 + c8);
        uint4 v1 = *(const uint4*)(src + (long)csr[j + 1] * 128 + c8);
        acc_h8(a0, v0);
        acc_h8(a1, v1);
    }
    if (j < e2) {
        uint4 v0 = *(const uint4*)(src + (long)csr[j] * 128 + c8);
        acc_h8(a0, v0);
    }
    float inv = 1.0f / fmaxf((float)(e2 - b), 1.0f);
    uint4 o;
    o.x = pack_h2((a0[0] + a1[0]) * inv, (a0[1] + a1[1]) * inv);
    o.y = pack_h2((a0[2] + a1[2]) * inv, (a0[3] + a1[3]) * inv);
    o.z = pack_h2((a0[4] + a1[4]) * inv, (a0[5] + a1[5]) * inv);
    o.w = pack_h2((a0[6] + a1[6]) * inv, (a0[7] + a1[7]) * inv);
    *(uint4*)(dst + (long)node * 128 + c8) = o;
}

// ---------------------------------------------------------------------------
// Fused layer-3 aggregation + log_softmax: one warp per node.
//   mean over neighbors of t3r3[:, 0:40], plus bias + t3r3[node, 40:80],
//   then log_softmax over 40 classes.
// ---------------------------------------------------------------------------
__global__ void k_final(const int* __restrict__ rowptr, const int* __restrict__ csr,
                        const float* __restrict__ t3r3, const float* __restrict__ bias,
                        float* __restrict__ out, int Nn)
{
    int gw   = (int)((blockIdx.x * (long)blockDim.x + threadIdx.x) >> 5);
    int lane = threadIdx.x & 31;
    if (gw >= Nn) return;

    int b  = rowptr[gw];
    int e2 = rowptr[gw + 1];
    float a0 = 0.f, a1 = 0.f;       // a1 valid for lane < 8 (cols 32..39)
    float b0 = 0.f, b1 = 0.f;
    int j = b;
    for (; j + 2 <= e2; j += 2) {
        const float* r0 = t3r3 + (long)csr[j]     * 80;
        const float* r1 = t3r3 + (long)csr[j + 1] * 80;
        a0 += r0[lane];
        b0 += r1[lane];
        if (lane < 8) { a1 += r0[32 + lane]; b1 += r1[32 + lane]; }
    }
    if (j < e2) {
        const float* r0 = t3r3 + (long)csr[j] * 80;
        a0 += r0[lane];
        if (lane < 8) a1 += r0[32 + lane];
    }
    float inv = 1.0f / fmaxf((float)(e2 - b), 1.0f);

    const float* rr = t3r3 + (long)gw * 80 + 40;
    float x0 = (a0 + b0) * inv + bias[lane] + rr[lane];
    float x1 = -3.402823466e38f;
    if (lane < 8) x1 = (a1 + b1) * inv + bias[32 + lane] + rr[32 + lane];

    float m = fmaxf(x0, x1);
#pragma unroll
    for (int o = 16; o; o >>= 1) m = fmaxf(m, __shfl_xor_sync(0xffffffffu, m, o));

    float s = expf(x0 - m) + ((lane < 8) ? expf(x1 - m) : 0.0f);
#pragma unroll
    for (int o = 16; o; o >>= 1) s += __shfl_xor_sync(0xffffffffu, s, o);

    float lse = m + logf(s);
    out[(long)gw * 40 + lane] = x0 - lse;
    if (lane < 8) out[(long)gw * 40 + 32 + lane] = x1 - lse;
}

// ---------------------------------------------------------------------------
// Host launcher. GEMM0 at launch position 5 (ncu profiles 5th launch).
// ---------------------------------------------------------------------------
extern "C" void kernel_launch(void* const* d_in, const int* in_sizes, int n_in,
                              void* d_out, int out_size)
{
    const float* x     = (const float*)d_in[0];
    const int*   ei    = (const int*)  d_in[1];
    const float* W_map = (const float*)d_in[2];
    const float* b_map = (const float*)d_in[3];
    const float* Wl1   = (const float*)d_in[4];
    const float* bl1   = (const float*)d_in[5];
    const float* Wr1   = (const float*)d_in[6];
    const float* Wl2   = (const float*)d_in[7];
    const float* bl2   = (const float*)d_in[8];
    const float* Wr2   = (const float*)d_in[9];
    const float* Wl3   = (const float*)d_in[10];
    const float* bl3   = (const float*)d_in[11];
    const float* Wr3   = (const float*)d_in[12];
    float* out = (float*)d_out;

    const int E  = in_sizes[1] / 2;
    const int Nn = NN;

    void *p_h0, *p_h1, *p_h2, *p_aggh, *p_t3r3;
    void *p_deg, *p_rowptr, *p_cursor, *p_csr;
    void *p_b0h, *p_b1h, *p_b2h, *p_b3h;
    cudaGetSymbolAddress(&p_h0,   g_h0);
    cudaGetSymbolAddress(&p_h1,   g_h1);
    cudaGetSymbolAddress(&p_h2,   g_h2);
    cudaGetSymbolAddress(&p_aggh, g_aggh);
    cudaGetSymbolAddress(&p_t3r3, g_t3r3);
    cudaGetSymbolAddress(&p_deg,    g_deg);
    cudaGetSymbolAddress(&p_rowptr, g_rowptr);
    cudaGetSymbolAddress(&p_cursor, g_cursor);
    cudaGetSymbolAddress(&p_csr,    g_csr);
    cudaGetSymbolAddress(&p_b0h, g_B0h);
    cudaGetSymbolAddress(&p_b1h, g_B1h);
    cudaGetSymbolAddress(&p_b2h, g_B2h);
    cudaGetSymbolAddress(&p_b3h, g_B3h);

    __half* h0   = (__half*)p_h0;
    __half* h1   = (__half*)p_h1;
    __half* h2   = (__half*)p_h2;
    __half* aggh = (__half*)p_aggh;
    float*  t3r3 = (float*)p_t3r3;
    int* deg    = (int*)p_deg;
    int* rowptr = (int*)p_rowptr;
    int* cursor = (int*)p_cursor;
    int* csr    = (int*)p_csr;

    const int SMEM = 1024 + 2 * STG_BYTES;   // 41984
    cudaFuncSetAttribute(k_mgemm<0, false, true,  true>,  cudaFuncAttributeMaxDynamicSharedMemorySize, SMEM);
    cudaFuncSetAttribute(k_mgemm<1, true,  true,  true>,  cudaFuncAttributeMaxDynamicSharedMemorySize, SMEM);
    cudaFuncSetAttribute(k_mgemm<2, false, false, false>, cudaFuncAttributeMaxDynamicSharedMemorySize, SMEM);

    const int MT = (Nn + 127) / 128;   // 391 M-tiles
    dim3 g1(MT, 1), g2(MT, 2);

    // Launches 1-4: memset + merged prep + hist + scan (GEMM0 needs prep only)
    cudaMemsetAsync(p_deg, 0, (size_t)Nn * sizeof(int));                                   // 1
    k_prep_all<<<768, 256>>>(W_map, Wr1, Wl1, Wr2, Wl2, Wl3, Wr3,
                             (__half*)p_b0h, (__half*)p_b1h,
                             (__half*)p_b2h, (__half*)p_b3h);                              // 2
    k_hist<<<(E + 255) / 256, 256>>>(ei, E, deg);                                          // 3
    k_scan<<<1, 1024>>>(deg, rowptr, Nn);                                                  // 4

    // Launch 5 (PROFILED): h0 = fp16(x @ W_map + b_map)
    k_mgemm<0, false, true, true><<<g1, 256, SMEM>>>(
        x, nullptr, nullptr, (__half*)p_b0h, 512, 16, b_map, nullptr, h0, Nn, 128);

    // CSR fill
    cudaMemcpyAsync(cursor, rowptr, (size_t)Nn * sizeof(int), cudaMemcpyDeviceToDevice);
    k_fill<<<(E + 255) / 256, 256>>>(ei, E, cursor, csr);

    // layer 1
    k_agg_h<<<(int)(((long)Nn * 16 + 255) / 256), 256>>>(rowptr, csr, h0, aggh, Nn);
    k_mgemm<1, true, true, true><<<g1, 256, SMEM>>>(
        nullptr, h0, aggh, (__half*)p_b1h, 256, 8, bl1, nullptr, h1, Nn, 128);

    // layer 2
    k_agg_h<<<(int)(((long)Nn * 16 + 255) / 256), 256>>>(rowptr, csr, h1, aggh, Nn);
    k_mgemm<1, true, true, true><<<g2, 256, SMEM>>>(
        nullptr, h1, aggh, (__half*)p_b2h, 256, 8, bl2, nullptr, h2, Nn, 256);

    // layer 3: transform, then fused aggregate+log_softmax
    k_mgemm<2, false, false, false><<<g1, 256, SMEM>>>(
        nullptr, h2, nullptr, (__half*)p_b3h, 256, 8, nullptr, t3r3, nullptr, Nn, 80);
    k_final<<<(Nn * 32 + 255) / 256, 256>>>(rowptr, csr, t3r3, bl3, out, Nn);
}